// round 1
// baseline (speedup 1.0000x reference)
#include <cuda_runtime.h>

#define GHM_BINS 10
#define GHM_BLOCK 256
#define GHM_GRID (148 * 8)

// Global accumulators (allocation-free scratch).
__device__ float g_ghm_counts[GHM_BINS];
__device__ float g_ghm_sums[GHM_BINS];

__global__ void ghm_zero_kernel() {
    int i = threadIdx.x;
    if (i < GHM_BINS) {
        g_ghm_counts[i] = 0.0f;
        g_ghm_sums[i]   = 0.0f;
    }
}

__device__ __forceinline__ void ghm_accum_elem(float p, float t, float w,
                                               float2* hist_col /* &hist[0][tid], stride GHM_BLOCK */) {
    // e = exp(-|p|)
    float ap = fabsf(p);
    float e  = __expf(-ap);              // FMUL + MUFU.EX2
    float d  = 1.0f + e;
    float lp = __logf(d);                // log1p(exp(-|p|)) = log(1+e); MUFU.LG2
    // stable BCE-with-logits
    float bce = fmaxf(p, 0.0f) - p * t + lp;
    // sigmoid(p) from same e: p>=0 -> 1/(1+e), else e/(1+e) = 1 - 1/(1+e)
    float u = __fdividef(1.0f, d);       // MUFU.RCP
    float s = (p >= 0.0f) ? u : (1.0f - u);
    float g10 = fabsf(s - t) * 10.0f;    // g in [0,1] -> g10 in [0,10]
    int idx = (int)g10;                  // floor (g10 >= 0)
    idx = min(idx, GHM_BINS - 1);        // clip top edge (g10 can hit 10.0)
    float vf = (w > 0.0f) ? 1.0f : 0.0f;
    float2 h = hist_col[idx * GHM_BLOCK];
    h.x += vf;
    h.y = fmaf(vf, bce, h.y);
    hist_col[idx * GHM_BLOCK] = h;
}

__global__ __launch_bounds__(GHM_BLOCK)
void ghm_main_kernel(const float4* __restrict__ pred4,
                     const float4* __restrict__ targ4,
                     const float4* __restrict__ lw4,
                     const float* __restrict__ pred,
                     const float* __restrict__ targ,
                     const float* __restrict__ lw,
                     long long nvec, long long ntotal) {
    // Thread-private histogram stripes: hist[bin][tid] as {count, bce_sum}.
    // Address = (bin*GHM_BLOCK + tid)*8 bytes -> bank-conflict-free LDS.64/STS.64.
    __shared__ float2 hist[GHM_BINS][GHM_BLOCK];

    const int tid = threadIdx.x;
#pragma unroll
    for (int b = 0; b < GHM_BINS; b++) hist[b][tid] = make_float2(0.0f, 0.0f);
    __syncthreads();

    float2* hist_col = &hist[0][tid];

    long long stride = (long long)gridDim.x * (long long)blockDim.x;
    for (long long i = (long long)blockIdx.x * blockDim.x + tid; i < nvec; i += stride) {
        float4 p = pred4[i];
        float4 t = targ4[i];
        float4 w = lw4[i];
        ghm_accum_elem(p.x, t.x, w.x, hist_col);
        ghm_accum_elem(p.y, t.y, w.y, hist_col);
        ghm_accum_elem(p.z, t.z, w.z, hist_col);
        ghm_accum_elem(p.w, t.w, w.w, hist_col);
    }

    // Scalar tail (ntotal not divisible by 4) — handled by first threads of block 0.
    long long tail_base = nvec * 4;
    long long rem = ntotal - tail_base;
    if (blockIdx.x == 0 && (long long)tid < rem) {
        long long j = tail_base + tid;
        ghm_accum_elem(pred[j], targ[j], lw[j], hist_col);
    }

    __syncthreads();

    // Block tree reduction over the thread dimension for each bin.
    for (int off = GHM_BLOCK / 2; off > 0; off >>= 1) {
        if (tid < off) {
#pragma unroll
            for (int b = 0; b < GHM_BINS; b++) {
                float2 a = hist[b][tid];
                float2 c = hist[b][tid + off];
                hist[b][tid] = make_float2(a.x + c.x, a.y + c.y);
            }
        }
        __syncthreads();
    }

    if (tid < GHM_BINS) {
        atomicAdd(&g_ghm_counts[tid], hist[tid][0].x);
        atomicAdd(&g_ghm_sums[tid],   hist[tid][0].y);
    }
}

__global__ void ghm_finalize_kernel(float* __restrict__ out) {
    if (threadIdx.x == 0 && blockIdx.x == 0) {
        // loss = (sum over nonempty bins of S_b / count_b) / max(n, 1)
        // (tot cancels between w_per_bin = tot/count and the final /tot).
        float n = 0.0f;
        float acc = 0.0f;
#pragma unroll
        for (int b = 0; b < GHM_BINS; b++) {
            float c = g_ghm_counts[b];
            if (c > 0.0f) {
                n += 1.0f;
                acc += g_ghm_sums[b] / c;
            }
        }
        out[0] = acc / fmaxf(n, 1.0f);
    }
}

extern "C" void kernel_launch(void* const* d_in, const int* in_sizes, int n_in,
                              void* d_out, int out_size) {
    const float* pred = (const float*)d_in[0];
    const float* targ = (const float*)d_in[1];
    const float* lw   = (const float*)d_in[2];
    float* out = (float*)d_out;

    long long ntotal = (long long)in_sizes[0];
    long long nvec = ntotal / 4;

    ghm_zero_kernel<<<1, 32>>>();
    ghm_main_kernel<<<GHM_GRID, GHM_BLOCK>>>(
        (const float4*)pred, (const float4*)targ, (const float4*)lw,
        pred, targ, lw, nvec, ntotal);
    ghm_finalize_kernel<<<1, 32>>>(out);
    (void)n_in; (void)out_size;
}